// round 1
// baseline (speedup 1.0000x reference)
#include <cuda_runtime.h>

#define B_ 2
#define DE 128
#define DOo 256
#define T_ 16
#define H_ 64
#define W_ 64
#define NBLK 16384   // T * 32 * 32
#define HWREF 1024   // 32 * 32
#define K_ 32
#define KK 8
#define MEMOUT_ELEMS (B_*DOo*H_*W_)   // 2097152

// ---- scratch (static device globals; no runtime allocation) ----
__device__ float g_mb_in[B_][NBLK][4][DE];    // 67 MB  [b][block][px][c]
__device__ float g_mb_out[B_][NBLK][4][DOo];  // 134 MB
__device__ float g_qkT[B_][HWREF][NBLK];      // 134 MB [b][j][n]
__device__ int   g_sel[B_][HWREF][K_];        // selected block indices (desc-value order)

// ============================================================
// Kernel 0: blockify  m[b][c][t][h][w] -> mb[b][n][pm][c]
//   n = t*1024 + (h/2)*32 + (w/2),  pm = (h%2)*2 + (w%2)
// Tiled 32(c) x 32(w) smem transpose; coalesced both directions.
// ============================================================
__global__ void blockify_kernel(const float* __restrict__ in, int D, int is_out) {
    __shared__ float tile[32][33];
    float* out = is_out ? &g_mb_out[0][0][0][0] : &g_mb_in[0][0][0][0];
    int bx = blockIdx.x;
    int wt = bx & 1;  bx >>= 1;
    int h  = bx & 63; bx >>= 6;
    int t  = bx & 15; bx >>= 4;
    int nct = D >> 5;
    int ct = bx % nct;
    int b  = bx / nct;
    int tx = threadIdx.x, ty = threadIdx.y;
    #pragma unroll
    for (int r = 0; r < 4; r++) {
        int c = (ct << 5) + ty + (r << 3);
        tile[ty + (r << 3)][tx] =
            in[(((b * D + c) * T_ + t) * H_ + h) * W_ + (wt << 5) + tx];
    }
    __syncthreads();
    int hr = h >> 1, im = h & 1;
    #pragma unroll
    for (int r = 0; r < 4; r++) {
        int wi = ty + (r << 3);
        int w  = (wt << 5) + wi;
        int wr = w >> 1, jm = w & 1;
        int n  = t * 1024 + hr * 32 + wr;
        int pm = im * 2 + jm;
        out[((b * NBLK + n) * 4 + pm) * D + (ct << 5) + tx] = tile[tx][wi];
    }
}

// ============================================================
// Kernel 1: transpose qk[b][n][j] -> qkT[b][j][n]
// ============================================================
__global__ void qk_transpose_kernel(const float* __restrict__ qk) {
    __shared__ float tile[32][33];
    int bx = blockIdx.x;
    int jt = bx & 31;  bx >>= 5;
    int nt = bx & 511; bx >>= 9;
    int b  = bx;
    int tx = threadIdx.x, ty = threadIdx.y;
    #pragma unroll
    for (int r = 0; r < 4; r++) {
        int n = (nt << 5) + ty + (r << 3);
        tile[ty + (r << 3)][tx] = qk[(b * NBLK + n) * HWREF + (jt << 5) + tx];
    }
    __syncthreads();
    #pragma unroll
    for (int r = 0; r < 4; r++) {
        int j = (jt << 5) + ty + (r << 3);
        g_qkT[b][j][(nt << 5) + tx] = tile[tx][ty + (r << 3)];
    }
}

// ============================================================
// Kernel 2: exact top-32 per column. One CTA (256 thr) per (b,j).
// Column (16384 floats) staged in 64KB dynamic smem. 32 rounds of
// hierarchical argmax: per-thread local (max,idx) over its 64-slot
// chunk; block reduce; only the winner's owner rescans its chunk.
// Extraction order = descending value (ties -> lower index) ==
// jax.lax.top_k order.
// ============================================================
__global__ void topk_kernel(float* __restrict__ aux_out, int write_aux) {
    extern __shared__ float sv[];               // 16384 floats
    __shared__ float s_bv[K_];
    __shared__ int   s_bi[K_];
    __shared__ float warp_v[8];
    __shared__ int   warp_i[8];
    __shared__ int   cur_i_s;

    int col = blockIdx.x;
    int b = col >> 10, j = col & 1023;
    int tid = threadIdx.x;

    const float4* src = (const float4*)(&g_qkT[b][j][0]);
    float4* dst4 = (float4*)sv;
    #pragma unroll
    for (int k = 0; k < 16; k++) dst4[tid + 256 * k] = src[tid + 256 * k];
    __syncthreads();

    int base = tid * 64;
    float mv = -__int_as_float(0x7f800000);  // -inf
    int   mi = -1;
    #pragma unroll 8
    for (int i = 0; i < 64; i++) {
        float v = sv[base + i];
        if (v > mv) { mv = v; mi = base + i; }
    }

    for (int r = 0; r < K_; r++) {
        float v = mv; int i = mi;
        #pragma unroll
        for (int o = 16; o; o >>= 1) {
            float ov = __shfl_down_sync(0xffffffffu, v, o);
            int   oi = __shfl_down_sync(0xffffffffu, i, o);
            if (ov > v || (ov == v && oi < i)) { v = ov; i = oi; }
        }
        if ((tid & 31) == 0) { warp_v[tid >> 5] = v; warp_i[tid >> 5] = i; }
        __syncthreads();
        if (tid == 0) {
            float bv = warp_v[0]; int bi = warp_i[0];
            #pragma unroll
            for (int w = 1; w < 8; w++) {
                if (warp_v[w] > bv || (warp_v[w] == bv && warp_i[w] < bi)) {
                    bv = warp_v[w]; bi = warp_i[w];
                }
            }
            s_bv[r] = bv; s_bi[r] = bi; cur_i_s = bi;
        }
        __syncthreads();
        int wi = cur_i_s;
        if ((wi >> 6) == tid) {
            sv[wi] = -__int_as_float(0x7f800000);
            mv = -__int_as_float(0x7f800000); mi = -1;
            #pragma unroll 8
            for (int i2 = 0; i2 < 64; i2++) {
                float vv = sv[base + i2];
                if (vv > mv) { mv = vv; mi = base + i2; }
            }
        }
        __syncthreads();
    }

    if (tid < K_) g_sel[b][j][tid] = s_bi[tid];
    if (write_aux && tid < KK) {
        int o = (b * HWREF + j) * KK + tid;
        aux_out[MEMOUT_ELEMS + o]                    = (float)s_bi[tid];
        aux_out[MEMOUT_ELEMS + B_ * HWREF * KK + o]  = s_bv[tid];
    }
}

// ============================================================
// Kernel 3: sparse block attention. One CTA (256 thr) per query
// block (b, hr, wr). 128 keys (32 blocks x 4 px), 4 query pixels.
//  QK: warp-per-key, float4 dot from g_mb_in (coalesced 512B rows)
//  softmax: warp-per-query-pixel
//  PV: thread-per-out-channel, coalesced 128B V rows + LDS.128 bcast
// ============================================================
__global__ void attn_kernel(const float* __restrict__ q_in, float* __restrict__ out) {
    __shared__ float4 q_s4[4][32];   // [p][c/4]
    __shared__ float4 p_s[128];      // [m] -> (p0..p3) weights
    __shared__ int    sel[K_];

    int blk = blockIdx.x;
    int b  = blk >> 10, jq = blk & 1023;
    int hr = jq >> 5,   wr = jq & 31;
    int tid = threadIdx.x;

    if (tid < K_) sel[tid] = g_sel[b][jq][tid];
    if (tid < DE) {
        int c = tid;
        const float* qp = q_in + ((b * DE + c) * H_ + hr * 2) * W_ + wr * 2;
        float2 r0 = *(const float2*)qp;
        float2 r1 = *(const float2*)(qp + W_);
        ((float*)q_s4)[0 * DE + c] = r0.x;
        ((float*)q_s4)[1 * DE + c] = r0.y;
        ((float*)q_s4)[2 * DE + c] = r1.x;
        ((float*)q_s4)[3 * DE + c] = r1.y;
    }
    __syncthreads();

    int wid = tid >> 5, lane = tid & 31;
    float4 q0 = q_s4[0][lane];
    float4 q1 = q_s4[1][lane];
    float4 q2 = q_s4[2][lane];
    float4 q3 = q_s4[3][lane];
    const float scale = 0.08838834764831845f;  // 1/sqrt(128)

    // ---- QK ----
    #pragma unroll 4
    for (int mm = 0; mm < 16; mm++) {
        int m  = wid * 16 + mm;
        int ks = m >> 2, pm = m & 3;
        int n  = sel[ks];
        const float4* kp = (const float4*)(&g_mb_in[b][n][pm][0]);
        float4 kv = kp[lane];
        float a0 = kv.x*q0.x + kv.y*q0.y + kv.z*q0.z + kv.w*q0.w;
        float a1 = kv.x*q1.x + kv.y*q1.y + kv.z*q1.z + kv.w*q1.w;
        float a2 = kv.x*q2.x + kv.y*q2.y + kv.z*q2.z + kv.w*q2.w;
        float a3 = kv.x*q3.x + kv.y*q3.y + kv.z*q3.z + kv.w*q3.w;
        #pragma unroll
        for (int o = 16; o; o >>= 1) {
            a0 += __shfl_xor_sync(0xffffffffu, a0, o);
            a1 += __shfl_xor_sync(0xffffffffu, a1, o);
            a2 += __shfl_xor_sync(0xffffffffu, a2, o);
            a3 += __shfl_xor_sync(0xffffffffu, a3, o);
        }
        if (lane == 0)
            p_s[m] = make_float4(a0 * scale, a1 * scale, a2 * scale, a3 * scale);
    }
    __syncthreads();

    // ---- softmax over m (128) per query pixel p ----
    if (wid < 4) {
        int p = wid;
        float* ps = (float*)p_s;
        float x0 = ps[(lane      ) * 4 + p];
        float x1 = ps[(lane + 32 ) * 4 + p];
        float x2 = ps[(lane + 64 ) * 4 + p];
        float x3 = ps[(lane + 96 ) * 4 + p];
        float mx = fmaxf(fmaxf(x0, x1), fmaxf(x2, x3));
        #pragma unroll
        for (int o = 16; o; o >>= 1) mx = fmaxf(mx, __shfl_xor_sync(0xffffffffu, mx, o));
        float e0 = __expf(x0 - mx), e1 = __expf(x1 - mx);
        float e2 = __expf(x2 - mx), e3 = __expf(x3 - mx);
        float sm = e0 + e1 + e2 + e3;
        #pragma unroll
        for (int o = 16; o; o >>= 1) sm += __shfl_xor_sync(0xffffffffu, sm, o);
        float inv = 1.0f / sm;
        ps[(lane      ) * 4 + p] = e0 * inv;
        ps[(lane + 32 ) * 4 + p] = e1 * inv;
        ps[(lane + 64 ) * 4 + p] = e2 * inv;
        ps[(lane + 96 ) * 4 + p] = e3 * inv;
    }
    __syncthreads();

    // ---- PV ----
    int c = tid;  // 0..255 = D_o
    float a0 = 0.f, a1 = 0.f, a2 = 0.f, a3 = 0.f;
    #pragma unroll 4
    for (int ks = 0; ks < K_; ks++) {
        int n = sel[ks];
        const float* vbase = &g_mb_out[b][n][0][0];
        #pragma unroll
        for (int pm = 0; pm < 4; pm++) {
            float  v  = vbase[pm * DOo + c];
            float4 pw = p_s[ks * 4 + pm];
            a0 += v * pw.x; a1 += v * pw.y; a2 += v * pw.z; a3 += v * pw.w;
        }
    }
    float* ob = out + ((b * DOo + c) * H_ + hr * 2) * W_ + wr * 2;
    *(float2*)ob        = make_float2(a0, a1);
    *(float2*)(ob + W_) = make_float2(a2, a3);
}

// ============================================================
extern "C" void kernel_launch(void* const* d_in, const int* in_sizes, int n_in,
                              void* d_out, int out_size) {
    const float* m_in  = (const float*)d_in[0];
    const float* m_out = (const float*)d_in[1];
    const float* q_in  = (const float*)d_in[2];
    const float* qk    = (const float*)d_in[3];
    float* out = (float*)d_out;

    int write_aux = (out_size >= MEMOUT_ELEMS + 2 * B_ * HWREF * KK) ? 1 : 0;

    cudaFuncSetAttribute(topk_kernel,
                         cudaFuncAttributeMaxDynamicSharedMemorySize, 65536);

    dim3 tb(32, 8);
    // blockify m_in (D=128): 2 * 4 * 16 * 64 * 2 = 16384 tiles
    blockify_kernel<<<16384, tb>>>(m_in, DE, 0);
    // blockify m_out (D=256): 32768 tiles
    blockify_kernel<<<32768, tb>>>(m_out, DOo, 1);
    // qk transpose: 32 * 512 * 2 = 32768 tiles
    qk_transpose_kernel<<<32768, tb>>>(qk);
    // top-k: one CTA per (b, j)
    topk_kernel<<<B_ * HWREF, 256, 65536>>>(out, write_aux);
    // attention: one CTA per query block
    attn_kernel<<<B_ * HWREF, 256>>>(q_in, out);
}